// round 1
// baseline (speedup 1.0000x reference)
#include <cuda_runtime.h>
#include <cstdint>

#define HIDDEN   2048
#define NHEADS   16
#define HEAD_DIM 128
#define BATCH    4
#define SEQ      2048
#define TOKENS   (BATCH * SEQ)     /* 8192 */
#define QKV_N    (3 * HIDDEN)      /* 6144 */
#define BH       (BATCH * NHEADS)  /* 64   */

// ---------------------------------------------------------------------------
// Scratch (device globals -- allocation-free per harness rules)
// ---------------------------------------------------------------------------
__device__ float g_qkv[(size_t)TOKENS * QKV_N];              // 201 MB: qkv projection
__device__ float g_qt [(size_t)BH * HEAD_DIM * SEQ];         // 67 MB:  Q in [bh][d][s]
__device__ float g_kt [(size_t)BH * HEAD_DIM * SEQ];         // 67 MB:  K in [bh][d][s]
__device__ float g_attn[(size_t)TOKENS * HIDDEN];            // 67 MB:  attention output

// ---------------------------------------------------------------------------
// fp32 NT GEMM with bias: C[m][n] = sum_k A[m][k]*B[n][k] + bias[n]
// 128x128 block tile, BK=16, 256 threads, 8x8 per thread (2x2 of 4x4).
// k-major smem (transposed on store) so compute reads are float4, phase-level
// conflict-free.
// ---------------------------------------------------------------------------
__global__ void __launch_bounds__(256, 2) sgemm_nt_bias(
    const float* __restrict__ A, const float* __restrict__ B,
    const float* __restrict__ bias, float* __restrict__ C,
    int M, int N, int K)
{
    __shared__ float As[16][132];
    __shared__ float Bs[16][132];

    const int tid = threadIdx.x;
    const int tx  = tid & 15;
    const int ty  = tid >> 4;
    const int bm  = blockIdx.y << 7;
    const int bn  = blockIdx.x << 7;

    float acc[8][8];
#pragma unroll
    for (int i = 0; i < 8; ++i)
#pragma unroll
        for (int j = 0; j < 8; ++j) acc[i][j] = 0.f;

    const int lrow = tid >> 2;          // 0..63, +64 on second pass
    const int lk4  = (tid & 3) << 2;    // 0,4,8,12

    for (int kt = 0; kt < K; kt += 16) {
#pragma unroll
        for (int p = 0; p < 2; ++p) {
            int row = lrow + (p << 6);
            float4 va = *(const float4*)&A[(size_t)(bm + row) * K + kt + lk4];
            As[lk4 + 0][row] = va.x;
            As[lk4 + 1][row] = va.y;
            As[lk4 + 2][row] = va.z;
            As[lk4 + 3][row] = va.w;
            float4 vb = *(const float4*)&B[(size_t)(bn + row) * K + kt + lk4];
            Bs[lk4 + 0][row] = vb.x;
            Bs[lk4 + 1][row] = vb.y;
            Bs[lk4 + 2][row] = vb.z;
            Bs[lk4 + 3][row] = vb.w;
        }
        __syncthreads();
#pragma unroll
        for (int k = 0; k < 16; ++k) {
            float4 a0 = *(const float4*)&As[k][ty << 2];
            float4 a1 = *(const float4*)&As[k][64 + (ty << 2)];
            float4 b0 = *(const float4*)&Bs[k][tx << 2];
            float4 b1 = *(const float4*)&Bs[k][64 + (tx << 2)];
            float a[8] = {a0.x, a0.y, a0.z, a0.w, a1.x, a1.y, a1.z, a1.w};
            float b[8] = {b0.x, b0.y, b0.z, b0.w, b1.x, b1.y, b1.z, b1.w};
#pragma unroll
            for (int i = 0; i < 8; ++i)
#pragma unroll
                for (int j = 0; j < 8; ++j)
                    acc[i][j] += a[i] * b[j];
        }
        __syncthreads();
    }

#pragma unroll
    for (int i = 0; i < 8; ++i) {
        int row = bm + ((i < 4) ? ((ty << 2) + i) : (64 + (ty << 2) + i - 4));
#pragma unroll
        for (int jh = 0; jh < 2; ++jh) {
            int col = bn + (jh << 6) + (tx << 2);
            float4 v;
            v.x = acc[i][jh * 4 + 0] + bias[col + 0];
            v.y = acc[i][jh * 4 + 1] + bias[col + 1];
            v.z = acc[i][jh * 4 + 2] + bias[col + 2];
            v.w = acc[i][jh * 4 + 3] + bias[col + 3];
            *(float4*)&C[(size_t)row * N + col] = v;
        }
    }
}

// ---------------------------------------------------------------------------
// Transpose Q and K from qkv[(b*S+s)][t*2048 + h*128 + d] into [bh][d][s].
// 32x32 tiles through padded smem; makes attention tile loads fully coalesced.
// ---------------------------------------------------------------------------
__global__ void __launch_bounds__(256) transpose_qk_kernel(
    const float* __restrict__ qkv, float* __restrict__ qt, float* __restrict__ kt)
{
    __shared__ float t0[32][33];
    __shared__ float t1[32][33];

    const int s0 = blockIdx.x << 5;   // seq offset
    const int d0 = blockIdx.y << 5;   // head-dim offset (0..96)
    const int bh = blockIdx.z;
    const int b  = bh >> 4;
    const int h  = bh & 15;

    const int col  = threadIdx.x & 31;
    const int rowb = threadIdx.x >> 5;   // 0..7

    const size_t inbase = ((size_t)(b * SEQ + s0)) * QKV_N + h * HEAD_DIM + d0;
#pragma unroll
    for (int r = rowb; r < 32; r += 8) {
        t0[r][col] = qkv[inbase + (size_t)r * QKV_N + col];           // Q (t=0)
        t1[r][col] = qkv[inbase + (size_t)r * QKV_N + HIDDEN + col];  // K (t=1)
    }
    __syncthreads();

    const size_t outbase = ((size_t)bh * HEAD_DIM + d0) * SEQ + s0;
#pragma unroll
    for (int r = rowb; r < 32; r += 8) {
        qt[outbase + (size_t)r * SEQ + col] = t0[col][r];
        kt[outbase + (size_t)r * SEQ + col] = t1[col][r];
    }
}

// ---------------------------------------------------------------------------
// Flash attention (causal), fp32.
// Block: one (q-tile of 64) x (batch*head). 256 threads = 16x16.
// S-gemm: 64x64, thread tile 4x4.  O-gemm: 64x128, thread tile 4x8.
// Q/K in smem d-major [128][68]; V row-major [64][132]; P c-major swizzled.
// ---------------------------------------------------------------------------
#define ATTN_SMEM_FLOATS (128 * 68 * 2 + 64 * 132 + 64 * 64)
#define ATTN_SMEM_BYTES  (ATTN_SMEM_FLOATS * 4)

__global__ void __launch_bounds__(256) attn_kernel(
    const float* __restrict__ qt, const float* __restrict__ kt,
    const float* __restrict__ qkv, float* __restrict__ out)
{
    extern __shared__ float sm[];
    float* Qs = sm;                  // [128][68]
    float* Ks = sm + 128 * 68;       // [128][68]
    float* Vs = Ks + 128 * 68;       // [64][132]
    float* Ps = Vs + 64 * 132;       // [64][64] swizzled, P[r][c] stored c-major

    const int iq = blockIdx.x;       // query tile index
    const int bh = blockIdx.y;
    const int b  = bh >> 4;
    const int h  = bh & 15;
    const int tid = threadIdx.x;
    const int tx  = tid & 15;
    const int ty  = tid >> 4;
    const int q0  = iq << 6;
    const float scale = 0.08838834764831845f;   // 1/sqrt(128)

    // Load Q tile: Qs[d][r], coalesced from [bh][d][s]
    {
        const float* qbase = qt + (size_t)bh * HEAD_DIM * SEQ + q0;
#pragma unroll
        for (int p = 0; p < 8; ++p) {
            int idx = tid + (p << 8);
            int d   = idx >> 4;
            int r4  = (idx & 15) << 2;
            *(float4*)&Qs[d * 68 + r4] = *(const float4*)&qbase[(size_t)d * SEQ + r4];
        }
    }

    float acc_o[4][8];
    float m_run[4], l_run[4];
#pragma unroll
    for (int i = 0; i < 4; ++i) {
        m_run[i] = -1e30f;
        l_run[i] = 0.f;
#pragma unroll
        for (int j = 0; j < 8; ++j) acc_o[i][j] = 0.f;
    }

    for (int jt = 0; jt <= iq; ++jt) {
        // K tile: Ks[d][c], coalesced from [bh][d][s]
        const float* kbase = kt + (size_t)bh * HEAD_DIM * SEQ + (jt << 6);
#pragma unroll
        for (int p = 0; p < 8; ++p) {
            int idx = tid + (p << 8);
            int d   = idx >> 4;
            int r4  = (idx & 15) << 2;
            *(float4*)&Ks[d * 68 + r4] = *(const float4*)&kbase[(size_t)d * SEQ + r4];
        }
        // V tile: Vs[c][d], coalesced from qkv (t=2 slice)
        const float* vbase = qkv + ((size_t)(b * SEQ + (jt << 6))) * QKV_N
                           + 2 * HIDDEN + h * HEAD_DIM;
#pragma unroll
        for (int p = 0; p < 8; ++p) {
            int idx = tid + (p << 8);
            int c   = idx >> 5;
            int d4  = (idx & 31) << 2;
            *(float4*)&Vs[c * 132 + d4] = *(const float4*)&vbase[(size_t)c * QKV_N + d4];
        }
        __syncthreads();

        // ---- S = Q K^T (64x64), thread owns rows ty*4.., cols tx*4.. ----
        float s[4][4];
#pragma unroll
        for (int i = 0; i < 4; ++i)
#pragma unroll
            for (int j = 0; j < 4; ++j) s[i][j] = 0.f;

#pragma unroll 8
        for (int k = 0; k < 128; ++k) {
            float4 a  = *(const float4*)&Qs[k * 68 + (ty << 2)];
            float4 bk = *(const float4*)&Ks[k * 68 + (tx << 2)];
            float av[4] = {a.x, a.y, a.z, a.w};
            float bv[4] = {bk.x, bk.y, bk.z, bk.w};
#pragma unroll
            for (int i = 0; i < 4; ++i)
#pragma unroll
                for (int j = 0; j < 4; ++j)
                    s[i][j] += av[i] * bv[j];
        }

#pragma unroll
        for (int i = 0; i < 4; ++i)
#pragma unroll
            for (int j = 0; j < 4; ++j) s[i][j] *= scale;

        if (jt == iq) {  // causal mask on the diagonal tile
#pragma unroll
            for (int i = 0; i < 4; ++i)
#pragma unroll
                for (int j = 0; j < 4; ++j)
                    if (((tx << 2) + j) > ((ty << 2) + i)) s[i][j] = -1e30f;
        }

        // ---- online softmax per row (16 tx-lanes per row, butterfly) ----
#pragma unroll
        for (int i = 0; i < 4; ++i) {
            float mx = fmaxf(fmaxf(s[i][0], s[i][1]), fmaxf(s[i][2], s[i][3]));
            mx = fmaxf(mx, __shfl_xor_sync(0xffffffffu, mx, 1));
            mx = fmaxf(mx, __shfl_xor_sync(0xffffffffu, mx, 2));
            mx = fmaxf(mx, __shfl_xor_sync(0xffffffffu, mx, 4));
            mx = fmaxf(mx, __shfl_xor_sync(0xffffffffu, mx, 8));
            float m_new = fmaxf(m_run[i], mx);
            float corr  = __expf(m_run[i] - m_new);
            m_run[i] = m_new;
            float rs = 0.f;
#pragma unroll
            for (int j = 0; j < 4; ++j) {
                float pv = __expf(s[i][j] - m_new);
                s[i][j] = pv;
                rs += pv;
            }
            rs += __shfl_xor_sync(0xffffffffu, rs, 1);
            rs += __shfl_xor_sync(0xffffffffu, rs, 2);
            rs += __shfl_xor_sync(0xffffffffu, rs, 4);
            rs += __shfl_xor_sync(0xffffffffu, rs, 8);
            l_run[i] = l_run[i] * corr + rs;
#pragma unroll
            for (int j = 0; j < 8; ++j) acc_o[i][j] *= corr;
        }

        // ---- store P c-major with xor swizzle: Ps[c][r] ----
#pragma unroll
        for (int j = 0; j < 4; ++j) {
            int c = (tx << 2) + j;
            float* pp = &Ps[(c << 6) + ((ty ^ (c & 15)) << 2)];
#pragma unroll
            for (int i = 0; i < 4; ++i) pp[i] = s[i][j];
        }
        __syncthreads();

        // ---- O += P V (64x128), thread owns rows ty*4.., cols tx*4 & 64+tx*4 ----
#pragma unroll 4
        for (int c = 0; c < 64; ++c) {
            float4 a  = *(const float4*)&Ps[(c << 6) + ((ty ^ (c & 15)) << 2)];
            float4 b0 = *(const float4*)&Vs[c * 132 + (tx << 2)];
            float4 b1 = *(const float4*)&Vs[c * 132 + 64 + (tx << 2)];
            float av[4] = {a.x, a.y, a.z, a.w};
            float bv[8] = {b0.x, b0.y, b0.z, b0.w, b1.x, b1.y, b1.z, b1.w};
#pragma unroll
            for (int i = 0; i < 4; ++i)
#pragma unroll
                for (int j = 0; j < 8; ++j)
                    acc_o[i][j] += av[i] * bv[j];
        }
        __syncthreads();
    }

    // ---- epilogue: O / l -> attn[(b*S + q)][h*128 + d] ----
#pragma unroll
    for (int i = 0; i < 4; ++i) {
        float inv = 1.f / l_run[i];
        size_t row = (size_t)(b * SEQ + q0 + (ty << 2) + i);
        int colb = h * HEAD_DIM + (tx << 2);
        float4 v0, v1;
        v0.x = acc_o[i][0] * inv; v0.y = acc_o[i][1] * inv;
        v0.z = acc_o[i][2] * inv; v0.w = acc_o[i][3] * inv;
        v1.x = acc_o[i][4] * inv; v1.y = acc_o[i][5] * inv;
        v1.z = acc_o[i][6] * inv; v1.w = acc_o[i][7] * inv;
        *(float4*)&out[row * HIDDEN + colb]      = v0;
        *(float4*)&out[row * HIDDEN + colb + 64] = v1;
    }
}

// ---------------------------------------------------------------------------
// Launch
// ---------------------------------------------------------------------------
extern "C" void kernel_launch(void* const* d_in, const int* in_sizes, int n_in,
                              void* d_out, int out_size)
{
    const float* hidden  = (const float*)d_in[0];
    const float* w_qkv   = (const float*)d_in[1];
    const float* b_qkv   = (const float*)d_in[2];
    const float* w_dense = (const float*)d_in[3];
    const float* b_dense = (const float*)d_in[4];
    float* out = (float*)d_out;

    float *qkv_p, *qt_p, *kt_p, *attn_p;
    cudaGetSymbolAddress((void**)&qkv_p,  g_qkv);
    cudaGetSymbolAddress((void**)&qt_p,   g_qt);
    cudaGetSymbolAddress((void**)&kt_p,   g_kt);
    cudaGetSymbolAddress((void**)&attn_p, g_attn);

    cudaFuncSetAttribute(attn_kernel,
                         cudaFuncAttributeMaxDynamicSharedMemorySize,
                         ATTN_SMEM_BYTES);

    dim3 blk(256);

    // 1) QKV projection: [8192,6144] = hidden @ w_qkv^T + b
    sgemm_nt_bias<<<dim3(QKV_N / 128, TOKENS / 128), blk>>>(
        hidden, w_qkv, b_qkv, qkv_p, TOKENS, QKV_N, HIDDEN);

    // 2) Transpose Q,K to [bh][d][s]
    transpose_qk_kernel<<<dim3(SEQ / 32, HEAD_DIM / 32, BH), blk>>>(
        qkv_p, qt_p, kt_p);

    // 3) Causal flash attention
    attn_kernel<<<dim3(SEQ / 64, BH), blk, ATTN_SMEM_BYTES>>>(
        qt_p, kt_p, qkv_p, attn_p);

    // 4) Dense projection: out = attn @ w_dense^T + b
    sgemm_nt_bias<<<dim3(HIDDEN / 128, TOKENS / 128), blk>>>(
        attn_p, w_dense, b_dense, out, TOKENS, HIDDEN, HIDDEN);
}

// round 4
// speedup vs baseline: 2.5818x; 2.5818x over previous
#include <cuda_runtime.h>
#include <cstdint>

#define HIDDEN   2048
#define NHEADS   16
#define HEAD_DIM 128
#define BATCH    4
#define SEQ      2048
#define TOKENS   (BATCH * SEQ)     /* 8192 */
#define QKV_N    (3 * HIDDEN)      /* 6144 */
#define BH       (BATCH * NHEADS)  /* 64   */

// ---------------------------------------------------------------------------
// Scratch (device globals -- allocation-free per harness rules)
// ---------------------------------------------------------------------------
__device__ float g_qkv[(size_t)TOKENS * QKV_N];
__device__ float g_qt [(size_t)BH * HEAD_DIM * SEQ];
__device__ float g_kt [(size_t)BH * HEAD_DIM * SEQ];
__device__ float g_attn[(size_t)TOKENS * HIDDEN];

// ---------------------------------------------------------------------------
// helpers
// ---------------------------------------------------------------------------
__device__ __forceinline__ uint32_t smem_u32(const void* p) {
    uint32_t a;
    asm("{ .reg .u64 t; cvta.to.shared.u64 t, %1; cvt.u32.u64 %0, t; }"
        : "=r"(a) : "l"(p));
    return a;
}
#define CVT_BF2(d, up, lo) \
    asm("cvt.rn.bf16x2.f32 %0, %1, %2;" : "=r"(d) : "f"(up), "f"(lo))

#define LDSM4(r, addr) \
    asm volatile("ldmatrix.sync.aligned.m8n8.x4.shared.b16 {%0,%1,%2,%3}, [%4];" \
        : "=r"((r)[0]), "=r"((r)[1]), "=r"((r)[2]), "=r"((r)[3]) : "r"(addr))

#define MMA_BF16(cr, a, b0, b1) \
    asm volatile("mma.sync.aligned.m16n8k16.row.col.f32.bf16.bf16.f32 " \
        "{%0,%1,%2,%3}, {%4,%5,%6,%7}, {%8,%9}, {%0,%1,%2,%3};" \
        : "+f"((cr)[0]), "+f"((cr)[1]), "+f"((cr)[2]), "+f"((cr)[3]) \
        : "r"((a)[0]), "r"((a)[1]), "r"((a)[2]), "r"((a)[3]), "r"(b0), "r"(b1))

// split fp32x4 -> hi (trunc) + lo (rn of residual), store as uint2 pairs
__device__ __forceinline__ void split_sts(char* hip, char* lop, float4 v) {
    uint32_t h0 = __byte_perm(__float_as_uint(v.x), __float_as_uint(v.y), 0x7632);
    uint32_t h1 = __byte_perm(__float_as_uint(v.z), __float_as_uint(v.w), 0x7632);
    float lx = v.x - __uint_as_float(__float_as_uint(v.x) & 0xffff0000u);
    float ly = v.y - __uint_as_float(__float_as_uint(v.y) & 0xffff0000u);
    float lz = v.z - __uint_as_float(__float_as_uint(v.z) & 0xffff0000u);
    float lw = v.w - __uint_as_float(__float_as_uint(v.w) & 0xffff0000u);
    uint32_t l0, l1;
    CVT_BF2(l0, ly, lx);
    CVT_BF2(l1, lw, lz);
    *(uint2*)hip = make_uint2(h0, h1);
    *(uint2*)lop = make_uint2(l0, l1);
}

// ---------------------------------------------------------------------------
// bf16x3 NT GEMM + bias via mma.sync:  C[m][n] = sum_k A[m][k]*B[n][k] + bias[n]
// BM=BN=128, BK=32 fp32. 256 thr = 8 warps (4m x 2n), warp tile 32x64.
// smem rows stride 80B (40 bf16): ldmatrix row addrs cover all 32 banks.
// ---------------------------------------------------------------------------
#define GROWB   80                         /* bytes per 32-col bf16 row */
#define GMAT    (128 * GROWB)              /* 10240 B per matrix */
#define GSTAGE  (4 * GMAT)                 /* Ahi|Alo|Bhi|Blo = 40960 B */
#define GSMEM   (2 * GSTAGE)               /* 81920 B */

__global__ void __launch_bounds__(256, 1) gemm_mma_bias(
    const float* __restrict__ A, const float* __restrict__ B,
    const float* __restrict__ bias, float* __restrict__ C,
    int M, int N, int K)
{
    extern __shared__ char smem[];
    const uint32_t sbase = smem_u32(smem);

    const int tid  = threadIdx.x;
    const int wid  = tid >> 5;
    const int lane = tid & 31;
    const int bm = blockIdx.y << 7;
    const int bn = blockIdx.x << 7;

    const int m0 = (wid & 3) << 5;     // 0,32,64,96
    const int n0 = (wid >> 2) << 6;    // 0,64

    float c[2][8][4];
#pragma unroll
    for (int mt = 0; mt < 2; ++mt)
#pragma unroll
        for (int nt = 0; nt < 8; ++nt)
#pragma unroll
            for (int q = 0; q < 4; ++q) c[mt][nt][q] = 0.f;

    // per-lane ldmatrix byte offsets
    const int a_row = lane & 15;
    const int a_col = ((lane >> 4) & 1) << 3;          // bf16 col 0/8
    const int b_mat = lane >> 3;
    const int b_nrow = (lane & 7) + ((b_mat & 1) << 3);
    const int b_kcol = (b_mat >> 1) << 3;

    // gmem loader mapping: 2 threads per row, 16 fp32 each
    const int grow = tid >> 1;
    const int gcol = (tid & 1) << 4;
    const float* Ag = A + (size_t)(bm + grow) * K + gcol;
    const float* Bg = B + (size_t)(bn + grow) * K + gcol;
    const uint32_t st_off = (uint32_t)(grow * GROWB + gcol * 2);

    const int KT = K >> 5;
    float4 ra[4], rb[4];

    // prologue: load + convert tile 0
#pragma unroll
    for (int q = 0; q < 4; ++q) {
        ra[q] = *(const float4*)(Ag + (q << 2));
        rb[q] = *(const float4*)(Bg + (q << 2));
    }
    {
        char* stg = smem;
#pragma unroll
        for (int q = 0; q < 4; ++q) {
            split_sts(stg + st_off + (q << 3),
                      stg + GMAT + st_off + (q << 3), ra[q]);
            split_sts(stg + 2 * GMAT + st_off + (q << 3),
                      stg + 3 * GMAT + st_off + (q << 3), rb[q]);
        }
    }

    for (int it = 0; it < KT; ++it) {
        __syncthreads();
        const int buf = it & 1;

        if (it + 1 < KT) {
            const float* An = Ag + (size_t)(it + 1) * 32;
            const float* Bn = Bg + (size_t)(it + 1) * 32;
#pragma unroll
            for (int q = 0; q < 4; ++q) {
                ra[q] = *(const float4*)(An + (q << 2));
                rb[q] = *(const float4*)(Bn + (q << 2));
            }
        }

        // ---- compute on stage buf ----
        const uint32_t sA  = sbase + buf * GSTAGE;
        const uint32_t sAl = sA + GMAT;
        const uint32_t sB  = sA + 2 * GMAT;
        const uint32_t sBl = sA + 3 * GMAT;

#pragma unroll
        for (int ks = 0; ks < 2; ++ks) {
            const int kb = ks << 4;
            uint32_t ah[2][4], al[2][4], bh[4][4], bl[4][4];
            const uint32_t aoff = (uint32_t)(a_row * GROWB + (kb + a_col) * 2);
            const uint32_t boff = (uint32_t)(b_nrow * GROWB + (kb + b_kcol) * 2);
#pragma unroll
            for (int mt = 0; mt < 2; ++mt) {
                const uint32_t mo = (uint32_t)((m0 + mt * 16) * GROWB);
                LDSM4(ah[mt], sA  + mo + aoff);
                LDSM4(al[mt], sAl + mo + aoff);
            }
#pragma unroll
            for (int nq = 0; nq < 4; ++nq) {
                const uint32_t no = (uint32_t)((n0 + nq * 16) * GROWB);
                LDSM4(bh[nq], sB  + no + boff);
                LDSM4(bl[nq], sBl + no + boff);
            }
#pragma unroll
            for (int mt = 0; mt < 2; ++mt)
#pragma unroll
                for (int nt = 0; nt < 8; ++nt) {
                    const int nq = nt >> 1, sel = nt & 1;
                    MMA_BF16(c[mt][nt], ah[mt], bh[nq][sel], bh[nq][sel + 2]);
                    MMA_BF16(c[mt][nt], ah[mt], bl[nq][sel], bl[nq][sel + 2]);
                    MMA_BF16(c[mt][nt], al[mt], bh[nq][sel], bh[nq][sel + 2]);
                }
        }

        // ---- convert next tile into the other stage ----
        if (it + 1 < KT) {
            char* stg = smem + ((it + 1) & 1) * GSTAGE;
#pragma unroll
            for (int q = 0; q < 4; ++q) {
                split_sts(stg + st_off + (q << 3),
                          stg + GMAT + st_off + (q << 3), ra[q]);
                split_sts(stg + 2 * GMAT + st_off + (q << 3),
                          stg + 3 * GMAT + st_off + (q << 3), rb[q]);
            }
        }
    }

    // ---- epilogue: direct register -> gmem with bias ----
    const int grp = lane >> 2, tig = lane & 3;
#pragma unroll
    for (int nt = 0; nt < 8; ++nt) {
        const int col = bn + n0 + nt * 8 + tig * 2;
        const float2 bv = *(const float2*)&bias[col];
#pragma unroll
        for (int mt = 0; mt < 2; ++mt) {
            const int row = bm + m0 + mt * 16 + grp;
            float2 v0 = make_float2(c[mt][nt][0] + bv.x, c[mt][nt][1] + bv.y);
            float2 v1 = make_float2(c[mt][nt][2] + bv.x, c[mt][nt][3] + bv.y);
            *(float2*)&C[(size_t)row * N + col]       = v0;
            *(float2*)&C[(size_t)(row + 8) * N + col] = v1;
        }
    }
}

// ---------------------------------------------------------------------------
// Transpose Q and K from qkv[(b*S+s)][t*2048 + h*128 + d] into [bh][d][s].
// ---------------------------------------------------------------------------
__global__ void __launch_bounds__(256) transpose_qk_kernel(
    const float* __restrict__ qkv, float* __restrict__ qt, float* __restrict__ kt)
{
    __shared__ float t0[32][33];
    __shared__ float t1[32][33];

    const int s0 = blockIdx.x << 5;
    const int d0 = blockIdx.y << 5;
    const int bh = blockIdx.z;
    const int b  = bh >> 4;
    const int h  = bh & 15;

    const int col  = threadIdx.x & 31;
    const int rowb = threadIdx.x >> 5;

    const size_t inbase = ((size_t)(b * SEQ + s0)) * QKV_N + h * HEAD_DIM + d0;
#pragma unroll
    for (int r = rowb; r < 32; r += 8) {
        t0[r][col] = qkv[inbase + (size_t)r * QKV_N + col];
        t1[r][col] = qkv[inbase + (size_t)r * QKV_N + HIDDEN + col];
    }
    __syncthreads();

    const size_t outbase = ((size_t)bh * HEAD_DIM + d0) * SEQ + s0;
#pragma unroll
    for (int r = rowb; r < 32; r += 8) {
        qt[outbase + (size_t)r * SEQ + col] = t0[col][r];
        kt[outbase + (size_t)r * SEQ + col] = t1[col][r];
    }
}

// ---------------------------------------------------------------------------
// Flash attention (causal), fp32 (unchanged)
// ---------------------------------------------------------------------------
#define ATTN_SMEM_FLOATS (128 * 68 * 2 + 64 * 132 + 64 * 64)
#define ATTN_SMEM_BYTES  (ATTN_SMEM_FLOATS * 4)

__global__ void __launch_bounds__(256) attn_kernel(
    const float* __restrict__ qt, const float* __restrict__ kt,
    const float* __restrict__ qkv, float* __restrict__ out)
{
    extern __shared__ float sm[];
    float* Qs = sm;
    float* Ks = sm + 128 * 68;
    float* Vs = Ks + 128 * 68;
    float* Ps = Vs + 64 * 132;

    const int iq = blockIdx.x;
    const int bh = blockIdx.y;
    const int b  = bh >> 4;
    const int h  = bh & 15;
    const int tid = threadIdx.x;
    const int tx  = tid & 15;
    const int ty  = tid >> 4;
    const int q0  = iq << 6;
    const float scale = 0.08838834764831845f;

    {
        const float* qbase = qt + (size_t)bh * HEAD_DIM * SEQ + q0;
#pragma unroll
        for (int p = 0; p < 8; ++p) {
            int idx = tid + (p << 8);
            int d   = idx >> 4;
            int r4  = (idx & 15) << 2;
            *(float4*)&Qs[d * 68 + r4] = *(const float4*)&qbase[(size_t)d * SEQ + r4];
        }
    }

    float acc_o[4][8];
    float m_run[4], l_run[4];
#pragma unroll
    for (int i = 0; i < 4; ++i) {
        m_run[i] = -1e30f;
        l_run[i] = 0.f;
#pragma unroll
        for (int j = 0; j < 8; ++j) acc_o[i][j] = 0.f;
    }

    for (int jt = 0; jt <= iq; ++jt) {
        const float* kbase = kt + (size_t)bh * HEAD_DIM * SEQ + (jt << 6);
#pragma unroll
        for (int p = 0; p < 8; ++p) {
            int idx = tid + (p << 8);
            int d   = idx >> 4;
            int r4  = (idx & 15) << 2;
            *(float4*)&Ks[d * 68 + r4] = *(const float4*)&kbase[(size_t)d * SEQ + r4];
        }
        const float* vbase = qkv + ((size_t)(b * SEQ + (jt << 6))) * QKV_N
                           + 2 * HIDDEN + h * HEAD_DIM;
#pragma unroll
        for (int p = 0; p < 8; ++p) {
            int idx = tid + (p << 8);
            int cc  = idx >> 5;
            int d4  = (idx & 31) << 2;
            *(float4*)&Vs[cc * 132 + d4] = *(const float4*)&vbase[(size_t)cc * QKV_N + d4];
        }
        __syncthreads();

        float s[4][4];
#pragma unroll
        for (int i = 0; i < 4; ++i)
#pragma unroll
            for (int j = 0; j < 4; ++j) s[i][j] = 0.f;

#pragma unroll 8
        for (int k = 0; k < 128; ++k) {
            float4 a  = *(const float4*)&Qs[k * 68 + (ty << 2)];
            float4 bk = *(const float4*)&Ks[k * 68 + (tx << 2)];
            float av[4] = {a.x, a.y, a.z, a.w};
            float bv[4] = {bk.x, bk.y, bk.z, bk.w};
#pragma unroll
            for (int i = 0; i < 4; ++i)
#pragma unroll
                for (int j = 0; j < 4; ++j)
                    s[i][j] += av[i] * bv[j];
        }

#pragma unroll
        for (int i = 0; i < 4; ++i)
#pragma unroll
            for (int j = 0; j < 4; ++j) s[i][j] *= scale;

        if (jt == iq) {
#pragma unroll
            for (int i = 0; i < 4; ++i)
#pragma unroll
                for (int j = 0; j < 4; ++j)
                    if (((tx << 2) + j) > ((ty << 2) + i)) s[i][j] = -1e30f;
        }

#pragma unroll
        for (int i = 0; i < 4; ++i) {
            float mx = fmaxf(fmaxf(s[i][0], s[i][1]), fmaxf(s[i][2], s[i][3]));
            mx = fmaxf(mx, __shfl_xor_sync(0xffffffffu, mx, 1));
            mx = fmaxf(mx, __shfl_xor_sync(0xffffffffu, mx, 2));
            mx = fmaxf(mx, __shfl_xor_sync(0xffffffffu, mx, 4));
            mx = fmaxf(mx, __shfl_xor_sync(0xffffffffu, mx, 8));
            float m_new = fmaxf(m_run[i], mx);
            float corr  = __expf(m_run[i] - m_new);
            m_run[i] = m_new;
            float rs = 0.f;
#pragma unroll
            for (int j = 0; j < 4; ++j) {
                float pv = __expf(s[i][j] - m_new);
                s[i][j] = pv;
                rs += pv;
            }
            rs += __shfl_xor_sync(0xffffffffu, rs, 1);
            rs += __shfl_xor_sync(0xffffffffu, rs, 2);
            rs += __shfl_xor_sync(0xffffffffu, rs, 4);
            rs += __shfl_xor_sync(0xffffffffu, rs, 8);
            l_run[i] = l_run[i] * corr + rs;
#pragma unroll
            for (int j = 0; j < 8; ++j) acc_o[i][j] *= corr;
        }

#pragma unroll
        for (int j = 0; j < 4; ++j) {
            int cc = (tx << 2) + j;
            float* pp = &Ps[(cc << 6) + ((ty ^ (cc & 15)) << 2)];
#pragma unroll
            for (int i = 0; i < 4; ++i) pp[i] = s[i][j];
        }
        __syncthreads();

#pragma unroll 4
        for (int cc = 0; cc < 64; ++cc) {
            float4 a  = *(const float4*)&Ps[(cc << 6) + ((ty ^ (cc & 15)) << 2)];
            float4 b0 = *(const float4*)&Vs[cc * 132 + (tx << 2)];
            float4 b1 = *(const float4*)&Vs[cc * 132 + 64 + (tx << 2)];
            float av[4] = {a.x, a.y, a.z, a.w};
            float bv[8] = {b0.x, b0.y, b0.z, b0.w, b1.x, b1.y, b1.z, b1.w};
#pragma unroll
            for (int i = 0; i < 4; ++i)
#pragma unroll
                for (int j = 0; j < 8; ++j)
                    acc_o[i][j] += av[i] * bv[j];
        }
        __syncthreads();
    }

#pragma unroll
    for (int i = 0; i < 4; ++i) {
        float inv = 1.f / l_run[i];
        size_t row = (size_t)(b * SEQ + q0 + (ty << 2) + i);
        int colb = h * HEAD_DIM + (tx << 2);
        float4 v0, v1;
        v0.x = acc_o[i][0] * inv; v0.y = acc_o[i][1] * inv;
        v0.z = acc_o[i][2] * inv; v0.w = acc_o[i][3] * inv;
        v1.x = acc_o[i][4] * inv; v1.y = acc_o[i][5] * inv;
        v1.z = acc_o[i][6] * inv; v1.w = acc_o[i][7] * inv;
        *(float4*)&out[row * HIDDEN + colb]      = v0;
        *(float4*)&out[row * HIDDEN + colb + 64] = v1;
    }
}

// ---------------------------------------------------------------------------
// Launch
// ---------------------------------------------------------------------------
extern "C" void kernel_launch(void* const* d_in, const int* in_sizes, int n_in,
                              void* d_out, int out_size)
{
    const float* hidden  = (const float*)d_in[0];
    const float* w_qkv   = (const float*)d_in[1];
    const float* b_qkv   = (const float*)d_in[2];
    const float* w_dense = (const float*)d_in[3];
    const float* b_dense = (const float*)d_in[4];
    float* out = (float*)d_out;

    float *qkv_p, *qt_p, *kt_p, *attn_p;
    cudaGetSymbolAddress((void**)&qkv_p,  g_qkv);
    cudaGetSymbolAddress((void**)&qt_p,   g_qt);
    cudaGetSymbolAddress((void**)&kt_p,   g_kt);
    cudaGetSymbolAddress((void**)&attn_p, g_attn);

    cudaFuncSetAttribute(gemm_mma_bias,
                         cudaFuncAttributeMaxDynamicSharedMemorySize, GSMEM);
    cudaFuncSetAttribute(attn_kernel,
                         cudaFuncAttributeMaxDynamicSharedMemorySize,
                         ATTN_SMEM_BYTES);

    dim3 blk(256);

    // 1) QKV projection (mma.sync bf16x3)
    gemm_mma_bias<<<dim3(QKV_N / 128, TOKENS / 128), blk, GSMEM>>>(
        hidden, w_qkv, b_qkv, qkv_p, TOKENS, QKV_N, HIDDEN);

    // 2) Transpose Q,K to [bh][d][s]
    transpose_qk_kernel<<<dim3(SEQ / 32, HEAD_DIM / 32, BH), blk>>>(
        qkv_p, qt_p, kt_p);

    // 3) Causal flash attention (fp32)
    attn_kernel<<<dim3(SEQ / 64, BH), blk, ATTN_SMEM_BYTES>>>(
        qt_p, kt_p, qkv_p, attn_p);

    // 4) Dense projection (mma.sync bf16x3)
    gemm_mma_bias<<<dim3(HIDDEN / 128, TOKENS / 128), blk, GSMEM>>>(
        attn_p, w_dense, b_dense, out, TOKENS, HIDDEN, HIDDEN);
}

// round 6
// speedup vs baseline: 3.6851x; 1.4273x over previous
#include <cuda_runtime.h>
#include <cuda_bf16.h>
#include <cuda_fp16.h>
#include <cstdint>

#define HIDDEN   2048
#define NHEADS   16
#define HEAD_DIM 128
#define BATCH    4
#define SEQ      2048
#define TOKENS   (BATCH * SEQ)     /* 8192 */
#define QKV_N    (3 * HIDDEN)      /* 6144 */
#define BH       (BATCH * NHEADS)  /* 64   */
#define SOFTMAX_SCALE 0.08838834764831845f
#define LOG2E 1.4426950408889634f

// ---------------------------------------------------------------------------
// Scratch (device globals)
// ---------------------------------------------------------------------------
__device__ float g_qkv[(size_t)TOKENS * QKV_N];
__device__ float g_attn[(size_t)TOKENS * HIDDEN];
__device__ __nv_bfloat16 g_qh[(size_t)BH * SEQ * HEAD_DIM];
__device__ __nv_bfloat16 g_ql[(size_t)BH * SEQ * HEAD_DIM];
__device__ __nv_bfloat16 g_kh[(size_t)BH * SEQ * HEAD_DIM];
__device__ __nv_bfloat16 g_kl[(size_t)BH * SEQ * HEAD_DIM];
__device__ __half g_vh[(size_t)BH * HEAD_DIM * SEQ];   // transposed [bh][d][s]
__device__ __half g_vl[(size_t)BH * HEAD_DIM * SEQ];

// ---------------------------------------------------------------------------
// helpers
// ---------------------------------------------------------------------------
__device__ __forceinline__ uint32_t smem_u32(const void* p) {
    uint32_t a;
    asm("{ .reg .u64 t; cvta.to.shared.u64 t, %1; cvt.u32.u64 %0, t; }"
        : "=r"(a) : "l"(p));
    return a;
}
#define CVT_BF2(d, up, lo) \
    asm("cvt.rn.bf16x2.f32 %0, %1, %2;" : "=r"(d) : "f"(up), "f"(lo))
#define PACK_F16(d, up, lo) \
    asm("cvt.rn.f16x2.f32 %0, %1, %2;" : "=r"(d) : "f"(up), "f"(lo))

__device__ __forceinline__ float fast_exp2(float x) {
    float y;
    asm("ex2.approx.ftz.f32 %0, %1;" : "=f"(y) : "f"(x));
    return y;
}

#define LDSM4(r, addr) \
    asm volatile("ldmatrix.sync.aligned.m8n8.x4.shared.b16 {%0,%1,%2,%3}, [%4];" \
        : "=r"((r)[0]), "=r"((r)[1]), "=r"((r)[2]), "=r"((r)[3]) : "r"(addr))

#define MMA_BF16(cr, a, b0, b1) \
    asm volatile("mma.sync.aligned.m16n8k16.row.col.f32.bf16.bf16.f32 " \
        "{%0,%1,%2,%3}, {%4,%5,%6,%7}, {%8,%9}, {%0,%1,%2,%3};" \
        : "+f"((cr)[0]), "+f"((cr)[1]), "+f"((cr)[2]), "+f"((cr)[3]) \
        : "r"((a)[0]), "r"((a)[1]), "r"((a)[2]), "r"((a)[3]), "r"(b0), "r"(b1))

#define MMA_F16(cr, a, b0, b1) \
    asm volatile("mma.sync.aligned.m16n8k16.row.col.f32.f16.f16.f32 " \
        "{%0,%1,%2,%3}, {%4,%5,%6,%7}, {%8,%9}, {%0,%1,%2,%3};" \
        : "+f"((cr)[0]), "+f"((cr)[1]), "+f"((cr)[2]), "+f"((cr)[3]) \
        : "r"((a)[0]), "r"((a)[1]), "r"((a)[2]), "r"((a)[3]), "r"(b0), "r"(b1))

__device__ __forceinline__ void split_sts(char* hip, char* lop, float4 v) {
    uint32_t h0 = __byte_perm(__float_as_uint(v.x), __float_as_uint(v.y), 0x7632);
    uint32_t h1 = __byte_perm(__float_as_uint(v.z), __float_as_uint(v.w), 0x7632);
    float lx = v.x - __uint_as_float(__float_as_uint(v.x) & 0xffff0000u);
    float ly = v.y - __uint_as_float(__float_as_uint(v.y) & 0xffff0000u);
    float lz = v.z - __uint_as_float(__float_as_uint(v.z) & 0xffff0000u);
    float lw = v.w - __uint_as_float(__float_as_uint(v.w) & 0xffff0000u);
    uint32_t l0, l1;
    CVT_BF2(l0, ly, lx);
    CVT_BF2(l1, lw, lz);
    *(uint2*)hip = make_uint2(h0, h1);
    *(uint2*)lop = make_uint2(l0, l1);
}

// ---------------------------------------------------------------------------
// bf16x3 NT GEMM + bias via mma.sync (unchanged from R4 — validated)
// ---------------------------------------------------------------------------
#define GROWB   80
#define GMAT    (128 * GROWB)
#define GSTAGE  (4 * GMAT)
#define GSMEM   (2 * GSTAGE)

__global__ void __launch_bounds__(256, 1) gemm_mma_bias(
    const float* __restrict__ A, const float* __restrict__ B,
    const float* __restrict__ bias, float* __restrict__ C,
    int M, int N, int K)
{
    extern __shared__ char smem[];
    const uint32_t sbase = smem_u32(smem);

    const int tid  = threadIdx.x;
    const int wid  = tid >> 5;
    const int lane = tid & 31;
    const int bm = blockIdx.y << 7;
    const int bn = blockIdx.x << 7;

    const int m0 = (wid & 3) << 5;
    const int n0 = (wid >> 2) << 6;

    float c[2][8][4];
#pragma unroll
    for (int mt = 0; mt < 2; ++mt)
#pragma unroll
        for (int nt = 0; nt < 8; ++nt)
#pragma unroll
            for (int q = 0; q < 4; ++q) c[mt][nt][q] = 0.f;

    const int a_row = lane & 15;
    const int a_col = ((lane >> 4) & 1) << 3;
    const int b_mat = lane >> 3;
    const int b_nrow = (lane & 7) + ((b_mat & 1) << 3);
    const int b_kcol = (b_mat >> 1) << 3;

    const int grow = tid >> 1;
    const int gcol = (tid & 1) << 4;
    const float* Ag = A + (size_t)(bm + grow) * K + gcol;
    const float* Bg = B + (size_t)(bn + grow) * K + gcol;
    const uint32_t st_off = (uint32_t)(grow * GROWB + gcol * 2);

    const int KT = K >> 5;
    float4 ra[4], rb[4];

#pragma unroll
    for (int q = 0; q < 4; ++q) {
        ra[q] = *(const float4*)(Ag + (q << 2));
        rb[q] = *(const float4*)(Bg + (q << 2));
    }
    {
        char* stg = smem;
#pragma unroll
        for (int q = 0; q < 4; ++q) {
            split_sts(stg + st_off + (q << 3),
                      stg + GMAT + st_off + (q << 3), ra[q]);
            split_sts(stg + 2 * GMAT + st_off + (q << 3),
                      stg + 3 * GMAT + st_off + (q << 3), rb[q]);
        }
    }

    for (int it = 0; it < KT; ++it) {
        __syncthreads();
        const int buf = it & 1;

        if (it + 1 < KT) {
            const float* An = Ag + (size_t)(it + 1) * 32;
            const float* Bn = Bg + (size_t)(it + 1) * 32;
#pragma unroll
            for (int q = 0; q < 4; ++q) {
                ra[q] = *(const float4*)(An + (q << 2));
                rb[q] = *(const float4*)(Bn + (q << 2));
            }
        }

        const uint32_t sA  = sbase + buf * GSTAGE;
        const uint32_t sAl = sA + GMAT;
        const uint32_t sB  = sA + 2 * GMAT;
        const uint32_t sBl = sA + 3 * GMAT;

#pragma unroll
        for (int ks = 0; ks < 2; ++ks) {
            const int kb = ks << 4;
            uint32_t ah[2][4], al[2][4], bh[4][4], bl[4][4];
            const uint32_t aoff = (uint32_t)(a_row * GROWB + (kb + a_col) * 2);
            const uint32_t boff = (uint32_t)(b_nrow * GROWB + (kb + b_kcol) * 2);
#pragma unroll
            for (int mt = 0; mt < 2; ++mt) {
                const uint32_t mo = (uint32_t)((m0 + mt * 16) * GROWB);
                LDSM4(ah[mt], sA  + mo + aoff);
                LDSM4(al[mt], sAl + mo + aoff);
            }
#pragma unroll
            for (int nq = 0; nq < 4; ++nq) {
                const uint32_t no = (uint32_t)((n0 + nq * 16) * GROWB);
                LDSM4(bh[nq], sB  + no + boff);
                LDSM4(bl[nq], sBl + no + boff);
            }
#pragma unroll
            for (int mt = 0; mt < 2; ++mt)
#pragma unroll
                for (int nt = 0; nt < 8; ++nt) {
                    const int nq = nt >> 1, sel = nt & 1;
                    MMA_BF16(c[mt][nt], ah[mt], bh[nq][sel], bh[nq][sel + 2]);
                    MMA_BF16(c[mt][nt], ah[mt], bl[nq][sel], bl[nq][sel + 2]);
                    MMA_BF16(c[mt][nt], al[mt], bh[nq][sel], bh[nq][sel + 2]);
                }
        }

        if (it + 1 < KT) {
            char* stg = smem + ((it + 1) & 1) * GSTAGE;
#pragma unroll
            for (int q = 0; q < 4; ++q) {
                split_sts(stg + st_off + (q << 3),
                          stg + GMAT + st_off + (q << 3), ra[q]);
                split_sts(stg + 2 * GMAT + st_off + (q << 3),
                          stg + 3 * GMAT + st_off + (q << 3), rb[q]);
            }
        }
    }

    const int grp = lane >> 2, tig = lane & 3;
#pragma unroll
    for (int nt = 0; nt < 8; ++nt) {
        const int col = bn + n0 + nt * 8 + tig * 2;
        const float2 bv = *(const float2*)&bias[col];
#pragma unroll
        for (int mt = 0; mt < 2; ++mt) {
            const int row = bm + m0 + mt * 16 + grp;
            float2 v0 = make_float2(c[mt][nt][0] + bv.x, c[mt][nt][1] + bv.y);
            float2 v1 = make_float2(c[mt][nt][2] + bv.x, c[mt][nt][3] + bv.y);
            *(float2*)&C[(size_t)row * N + col]       = v0;
            *(float2*)&C[(size_t)(row + 8) * N + col] = v1;
        }
    }
}

// ---------------------------------------------------------------------------
// Pre-pass 1: convert Q (scaled) and K to bf16 hi/lo, layout [bh][s][d].
// One warp per (bh, s) row; lane handles 4 d-values.
// ---------------------------------------------------------------------------
__global__ void __launch_bounds__(256) convert_qk(
    const float* __restrict__ qkv,
    __nv_bfloat16* __restrict__ qh, __nv_bfloat16* __restrict__ ql,
    __nv_bfloat16* __restrict__ kh, __nv_bfloat16* __restrict__ kl)
{
    const int gw   = blockIdx.x * 8 + (threadIdx.x >> 5);
    const int lane = threadIdx.x & 31;
    const int bh = gw >> 11;          // / SEQ
    const int s  = gw & 2047;
    const int b  = bh >> 4;
    const int h  = bh & 15;

    const float* src = qkv + ((size_t)(b * SEQ + s)) * QKV_N + h * HEAD_DIM + lane * 4;
    float4 q = *(const float4*)src;
    float4 k = *(const float4*)(src + HIDDEN);
    q.x *= SOFTMAX_SCALE; q.y *= SOFTMAX_SCALE;
    q.z *= SOFTMAX_SCALE; q.w *= SOFTMAX_SCALE;

    const size_t dst = ((size_t)gw) * HEAD_DIM + lane * 4;
    split_sts((char*)(qh + dst), (char*)(ql + dst), q);
    split_sts((char*)(kh + dst), (char*)(kl + dst), k);
}

// ---------------------------------------------------------------------------
// Pre-pass 2: V -> fp16 hi/lo, transposed to [bh][d][s].
// ---------------------------------------------------------------------------
__global__ void __launch_bounds__(256) convert_v(
    const float* __restrict__ qkv,
    __half* __restrict__ vh, __half* __restrict__ vl)
{
    __shared__ float t[32][33];

    const int s0 = blockIdx.x << 5;
    const int d0 = blockIdx.y << 5;
    const int bh = blockIdx.z;
    const int b  = bh >> 4;
    const int h  = bh & 15;

    const int col  = threadIdx.x & 31;
    const int rowb = threadIdx.x >> 5;

    const size_t inbase = ((size_t)(b * SEQ + s0)) * QKV_N + 2 * HIDDEN + h * HEAD_DIM + d0;
#pragma unroll
    for (int r = rowb; r < 32; r += 8)
        t[r][col] = qkv[inbase + (size_t)r * QKV_N + col];
    __syncthreads();

    const size_t outbase = ((size_t)bh * HEAD_DIM + d0) * SEQ + s0;
#pragma unroll
    for (int r = rowb; r < 32; r += 8) {
        float v = t[col][r];
        __half hi = __float2half_rn(v);
        __half lo = __float2half_rn(v - __half2float(hi));
        vh[outbase + (size_t)r * SEQ + col] = hi;
        vl[outbase + (size_t)r * SEQ + col] = lo;
    }
}

// ---------------------------------------------------------------------------
// Flash attention on tensor cores.
// q-tile 128, key-tile 64, 8 warps (each warp: 16 q-rows).
// S = Q K^T : bf16x3.  P (fp16, reg->reg) x V (fp16 hi/lo) : 2 MMAs.
// ---------------------------------------------------------------------------
#define QSTR 272    /* bytes per 128-bf16 row (+16B pad) */
#define VSTR 144    /* bytes per 64-fp16 row (+16B pad)  */
#define SQH 0
#define SQL (SQH + 128 * QSTR)
#define SKH (SQL + 128 * QSTR)
#define SKL (SKH + 64 * QSTR)
#define SVH (SKL + 64 * QSTR)
#define SVL (SVH + 128 * VSTR)
#define ATTN_SMEM (SVL + 128 * VSTR)     /* 141312 B */

__global__ void __launch_bounds__(256, 1) attn_mma(
    const __nv_bfloat16* __restrict__ qh, const __nv_bfloat16* __restrict__ ql,
    const __nv_bfloat16* __restrict__ kh, const __nv_bfloat16* __restrict__ kl,
    const __half* __restrict__ vh, const __half* __restrict__ vl,
    float* __restrict__ out)
{
    extern __shared__ char sm[];
    const uint32_t sbase = smem_u32(sm);

    const int iq = blockIdx.x;
    const int bh = blockIdx.y;
    const int b  = bh >> 4;
    const int h  = bh & 15;
    const int tid  = threadIdx.x;
    const int wid  = tid >> 5;
    const int lane = tid & 31;
    const int q0 = iq << 7;
    const int m0 = wid << 4;

    // ---- load Q tile (128 x 128 bf16, hi+lo) ----
    {
        const uint4* qhg = (const uint4*)(qh + ((size_t)bh * SEQ + q0) * HEAD_DIM);
        const uint4* qlg = (const uint4*)(ql + ((size_t)bh * SEQ + q0) * HEAD_DIM);
#pragma unroll
        for (int i = tid; i < 2048; i += 256) {
            const int row = i >> 4, seg = i & 15;
            *(uint4*)(sm + SQH + row * QSTR + seg * 16) = qhg[row * 16 + seg];
            *(uint4*)(sm + SQL + row * QSTR + seg * 16) = qlg[row * 16 + seg];
        }
    }

    float co[16][4];
#pragma unroll
    for (int t = 0; t < 16; ++t)
#pragma unroll
        for (int q = 0; q < 4; ++q) co[t][q] = 0.f;
    float mr0 = -1e30f, mr1 = -1e30f, lr0 = 0.f, lr1 = 0.f;

    const int a_row = lane & 15;
    const int a_col = ((lane >> 4) & 1) << 3;
    const int b_mat = lane >> 3;
    const int b_nrow = (lane & 7) + ((b_mat & 1) << 3);
    const int b_kcol = (b_mat >> 1) << 3;

    const int nkt = 2 * (iq + 1);
    for (int jt = 0; jt < nkt; ++jt) {
        const int kt0 = jt << 6;
        // ---- load K tile (64 x 128 bf16, hi+lo) ----
        {
            const uint4* khg = (const uint4*)(kh + ((size_t)bh * SEQ + kt0) * HEAD_DIM);
            const uint4* klg = (const uint4*)(kl + ((size_t)bh * SEQ + kt0) * HEAD_DIM);
#pragma unroll
            for (int i = tid; i < 1024; i += 256) {
                const int row = i >> 4, seg = i & 15;
                *(uint4*)(sm + SKH + row * QSTR + seg * 16) = khg[row * 16 + seg];
                *(uint4*)(sm + SKL + row * QSTR + seg * 16) = klg[row * 16 + seg];
            }
        }
        // ---- load V^T tile (128 x 64 fp16, hi+lo) ----
        {
#pragma unroll
            for (int i = tid; i < 1024; i += 256) {
                const int d = i >> 3, seg = i & 7;
                const uint4* vhg = (const uint4*)(vh + ((size_t)bh * HEAD_DIM + d) * SEQ + kt0);
                const uint4* vlg = (const uint4*)(vl + ((size_t)bh * HEAD_DIM + d) * SEQ + kt0);
                *(uint4*)(sm + SVH + d * VSTR + seg * 16) = vhg[seg];
                *(uint4*)(sm + SVL + d * VSTR + seg * 16) = vlg[seg];
            }
        }
        __syncthreads();

        // ---- S = Q K^T (16 x 64 per warp), bf16x3 ----
        float cs[8][4];
#pragma unroll
        for (int t = 0; t < 8; ++t)
#pragma unroll
            for (int q = 0; q < 4; ++q) cs[t][q] = 0.f;

#pragma unroll
        for (int ks = 0; ks < 8; ++ks) {
            const int kb = ks << 4;
            uint32_t ah[4], al[4], bhf[4][4], blf[4][4];
            const uint32_t aoff = (uint32_t)((m0 + a_row) * QSTR + (kb + a_col) * 2);
            LDSM4(ah, sbase + SQH + aoff);
            LDSM4(al, sbase + SQL + aoff);
            const uint32_t boff = (uint32_t)(b_nrow * QSTR + (kb + b_kcol) * 2);
#pragma unroll
            for (int nq = 0; nq < 4; ++nq) {
                const uint32_t no = (uint32_t)(nq * 16 * QSTR);
                LDSM4(bhf[nq], sbase + SKH + no + boff);
                LDSM4(blf[nq], sbase + SKL + no + boff);
            }
#pragma unroll
            for (int nt = 0; nt < 8; ++nt) {
                const int nq = nt >> 1, sel = nt & 1;
                MMA_BF16(cs[nt], ah, bhf[nq][sel], bhf[nq][sel + 2]);
                MMA_BF16(cs[nt], ah, blf[nq][sel], blf[nq][sel + 2]);
                MMA_BF16(cs[nt], al, bhf[nq][sel], bhf[nq][sel + 2]);
            }
        }

        // ---- causal mask (only the last two key tiles can cross diagonal) ----
        if (jt >= 2 * iq) {
            const int rg0 = q0 + m0 + (lane >> 2);
            const int rg1 = rg0 + 8;
            const int cb  = kt0 + ((lane & 3) << 1);
#pragma unroll
            for (int nt = 0; nt < 8; ++nt) {
                const int c0 = cb + nt * 8;
                if (c0     > rg0) cs[nt][0] = -1e30f;
                if (c0 + 1 > rg0) cs[nt][1] = -1e30f;
                if (c0     > rg1) cs[nt][2] = -1e30f;
                if (c0 + 1 > rg1) cs[nt][3] = -1e30f;
            }
        }

        // ---- online softmax (rows rg0, rg1 per thread; reduce over quad) ----
        float mx0 = cs[0][0], mx1 = cs[0][2];
#pragma unroll
        for (int nt = 0; nt < 8; ++nt) {
            mx0 = fmaxf(mx0, fmaxf(cs[nt][0], cs[nt][1]));
            mx1 = fmaxf(mx1, fmaxf(cs[nt][2], cs[nt][3]));
        }
        mx0 = fmaxf(mx0, __shfl_xor_sync(0xffffffffu, mx0, 1));
        mx0 = fmaxf(mx0, __shfl_xor_sync(0xffffffffu, mx0, 2));
        mx1 = fmaxf(mx1, __shfl_xor_sync(0xffffffffu, mx1, 1));
        mx1 = fmaxf(mx1, __shfl_xor_sync(0xffffffffu, mx1, 2));

        const float mn0 = fmaxf(mr0, mx0);
        const float mn1 = fmaxf(mr1, mx1);
        const float corr0 = fast_exp2((mr0 - mn0) * LOG2E);
        const float corr1 = fast_exp2((mr1 - mn1) * LOG2E);
        mr0 = mn0; mr1 = mn1;

        float rs0 = 0.f, rs1 = 0.f;
#pragma unroll
        for (int nt = 0; nt < 8; ++nt) {
            float p0 = fast_exp2((cs[nt][0] - mn0) * LOG2E);
            float p1 = fast_exp2((cs[nt][1] - mn0) * LOG2E);
            float p2 = fast_exp2((cs[nt][2] - mn1) * LOG2E);
            float p3 = fast_exp2((cs[nt][3] - mn1) * LOG2E);
            cs[nt][0] = p0; cs[nt][1] = p1; cs[nt][2] = p2; cs[nt][3] = p3;
            rs0 += p0 + p1; rs1 += p2 + p3;
        }
        rs0 += __shfl_xor_sync(0xffffffffu, rs0, 1);
        rs0 += __shfl_xor_sync(0xffffffffu, rs0, 2);
        rs1 += __shfl_xor_sync(0xffffffffu, rs1, 1);
        rs1 += __shfl_xor_sync(0xffffffffu, rs1, 2);
        lr0 = lr0 * corr0 + rs0;
        lr1 = lr1 * corr1 + rs1;
#pragma unroll
        for (int t = 0; t < 16; ++t) {
            co[t][0] *= corr0; co[t][1] *= corr0;
            co[t][2] *= corr1; co[t][3] *= corr1;
        }

        // ---- pack P (fp16) straight into A-fragments ----
        uint32_t pa[4][4];
#pragma unroll
        for (int t = 0; t < 4; ++t) {
            PACK_F16(pa[t][0], cs[2 * t][1],     cs[2 * t][0]);
            PACK_F16(pa[t][1], cs[2 * t][3],     cs[2 * t][2]);
            PACK_F16(pa[t][2], cs[2 * t + 1][1], cs[2 * t + 1][0]);
            PACK_F16(pa[t][3], cs[2 * t + 1][3], cs[2 * t + 1][2]);
        }

        // ---- O += P V  (16 x 128 per warp), fp16, V hi+lo ----
#pragma unroll
        for (int ks = 0; ks < 4; ++ks) {
            const uint32_t voff = (uint32_t)(b_nrow * VSTR + ((ks << 4) + b_kcol) * 2);
#pragma unroll
            for (int nq = 0; nq < 8; ++nq) {
                uint32_t vhf[4], vlf[4];
                const uint32_t no = (uint32_t)(nq * 16 * VSTR);
                LDSM4(vhf, sbase + SVH + no + voff);
                LDSM4(vlf, sbase + SVL + no + voff);
                MMA_F16(co[nq * 2],     pa[ks], vhf[0], vhf[2]);
                MMA_F16(co[nq * 2],     pa[ks], vlf[0], vlf[2]);
                MMA_F16(co[nq * 2 + 1], pa[ks], vhf[1], vhf[3]);
                MMA_F16(co[nq * 2 + 1], pa[ks], vlf[1], vlf[3]);
            }
        }
        __syncthreads();
    }

    // ---- epilogue ----
    const float inv0 = 1.f / lr0;
    const float inv1 = 1.f / lr1;
    const size_t row0 = (size_t)(b * SEQ + q0 + m0 + (lane >> 2));
#pragma unroll
    for (int t = 0; t < 16; ++t) {
        const int col = h * HEAD_DIM + t * 8 + ((lane & 3) << 1);
        *(float2*)&out[row0 * HIDDEN + col] =
            make_float2(co[t][0] * inv0, co[t][1] * inv0);
        *(float2*)&out[(row0 + 8) * HIDDEN + col] =
            make_float2(co[t][2] * inv1, co[t][3] * inv1);
    }
}

// ---------------------------------------------------------------------------
// Launch
// ---------------------------------------------------------------------------
extern "C" void kernel_launch(void* const* d_in, const int* in_sizes, int n_in,
                              void* d_out, int out_size)
{
    const float* hidden  = (const float*)d_in[0];
    const float* w_qkv   = (const float*)d_in[1];
    const float* b_qkv   = (const float*)d_in[2];
    const float* w_dense = (const float*)d_in[3];
    const float* b_dense = (const float*)d_in[4];
    float* out = (float*)d_out;

    float *qkv_p, *attn_p;
    __nv_bfloat16 *qh_p, *ql_p, *kh_p, *kl_p;
    __half *vh_p, *vl_p;
    cudaGetSymbolAddress((void**)&qkv_p,  g_qkv);
    cudaGetSymbolAddress((void**)&attn_p, g_attn);
    cudaGetSymbolAddress((void**)&qh_p, g_qh);
    cudaGetSymbolAddress((void**)&ql_p, g_ql);
    cudaGetSymbolAddress((void**)&kh_p, g_kh);
    cudaGetSymbolAddress((void**)&kl_p, g_kl);
    cudaGetSymbolAddress((void**)&vh_p, g_vh);
    cudaGetSymbolAddress((void**)&vl_p, g_vl);

    cudaFuncSetAttribute(gemm_mma_bias,
                         cudaFuncAttributeMaxDynamicSharedMemorySize, GSMEM);
    cudaFuncSetAttribute(attn_mma,
                         cudaFuncAttributeMaxDynamicSharedMemorySize, ATTN_SMEM);

    dim3 blk(256);

    // 1) QKV projection (mma.sync bf16x3)
    gemm_mma_bias<<<dim3(QKV_N / 128, TOKENS / 128), blk, GSMEM>>>(
        hidden, w_qkv, b_qkv, qkv_p, TOKENS, QKV_N, HIDDEN);

    // 2) Convert Q (scaled), K to bf16 hi/lo
    convert_qk<<<(BH * SEQ) / 8, blk>>>(qkv_p, qh_p, ql_p, kh_p, kl_p);

    // 3) Convert + transpose V to fp16 hi/lo
    convert_v<<<dim3(SEQ / 32, HEAD_DIM / 32, BH), blk>>>(qkv_p, vh_p, vl_p);

    // 4) Tensor-core flash attention
    attn_mma<<<dim3(SEQ / 128, BH), blk, ATTN_SMEM>>>(
        qh_p, ql_p, kh_p, kl_p, vh_p, vl_p, attn_p);

    // 5) Dense projection (mma.sync bf16x3)
    gemm_mma_bias<<<dim3(HIDDEN / 128, TOKENS / 128), blk, GSMEM>>>(
        attn_p, w_dense, b_dense, out, TOKENS, HIDDEN, HIDDEN);
}

// round 7
// speedup vs baseline: 3.7284x; 1.0118x over previous
#include <cuda_runtime.h>
#include <cuda_bf16.h>
#include <cuda_fp16.h>
#include <cstdint>

#define HIDDEN   2048
#define NHEADS   16
#define HEAD_DIM 128
#define BATCH    4
#define SEQ      2048
#define TOKENS   (BATCH * SEQ)     /* 8192 */
#define QKV_N    (3 * HIDDEN)      /* 6144 */
#define BH       (BATCH * NHEADS)  /* 64   */
#define SOFTMAX_SCALE 0.08838834764831845f
#define LOG2E 1.4426950408889634f

// ---------------------------------------------------------------------------
// Scratch (device globals)
// ---------------------------------------------------------------------------
__device__ float g_qkv[(size_t)TOKENS * QKV_N];
__device__ __nv_bfloat16 g_hh [(size_t)TOKENS * HIDDEN];   // hidden hi
__device__ __nv_bfloat16 g_hl [(size_t)TOKENS * HIDDEN];   // hidden lo
__device__ __nv_bfloat16 g_wqh[(size_t)QKV_N * HIDDEN];
__device__ __nv_bfloat16 g_wql[(size_t)QKV_N * HIDDEN];
__device__ __nv_bfloat16 g_wdh[(size_t)HIDDEN * HIDDEN];
__device__ __nv_bfloat16 g_wdl[(size_t)HIDDEN * HIDDEN];
__device__ __nv_bfloat16 g_ath[(size_t)TOKENS * HIDDEN];   // attn out hi
__device__ __nv_bfloat16 g_atl[(size_t)TOKENS * HIDDEN];   // attn out lo
__device__ __nv_bfloat16 g_qh[(size_t)BH * SEQ * HEAD_DIM];
__device__ __nv_bfloat16 g_ql[(size_t)BH * SEQ * HEAD_DIM];
__device__ __nv_bfloat16 g_kh[(size_t)BH * SEQ * HEAD_DIM];
__device__ __nv_bfloat16 g_kl[(size_t)BH * SEQ * HEAD_DIM];
__device__ __half g_vh[(size_t)BH * HEAD_DIM * SEQ];       // [bh][d][s]
__device__ __half g_vl[(size_t)BH * HEAD_DIM * SEQ];

// ---------------------------------------------------------------------------
// helpers
// ---------------------------------------------------------------------------
__device__ __forceinline__ uint32_t smem_u32(const void* p) {
    uint32_t a;
    asm("{ .reg .u64 t; cvta.to.shared.u64 t, %1; cvt.u32.u64 %0, t; }"
        : "=r"(a) : "l"(p));
    return a;
}
#define CVT_BF2(d, up, lo) \
    asm("cvt.rn.bf16x2.f32 %0, %1, %2;" : "=r"(d) : "f"(up), "f"(lo))
#define PACK_F16(d, up, lo) \
    asm("cvt.rn.f16x2.f32 %0, %1, %2;" : "=r"(d) : "f"(up), "f"(lo))

__device__ __forceinline__ float fast_exp2(float x) {
    float y;
    asm("ex2.approx.ftz.f32 %0, %1;" : "=f"(y) : "f"(x));
    return y;
}

#define LDSM4(r, addr) \
    asm volatile("ldmatrix.sync.aligned.m8n8.x4.shared.b16 {%0,%1,%2,%3}, [%4];" \
        : "=r"((r)[0]), "=r"((r)[1]), "=r"((r)[2]), "=r"((r)[3]) : "r"(addr))

#define MMA_BF16(cr, a, b0, b1) \
    asm volatile("mma.sync.aligned.m16n8k16.row.col.f32.bf16.bf16.f32 " \
        "{%0,%1,%2,%3}, {%4,%5,%6,%7}, {%8,%9}, {%0,%1,%2,%3};" \
        : "+f"((cr)[0]), "+f"((cr)[1]), "+f"((cr)[2]), "+f"((cr)[3]) \
        : "r"((a)[0]), "r"((a)[1]), "r"((a)[2]), "r"((a)[3]), "r"(b0), "r"(b1))

#define MMA_F16(cr, a, b0, b1) \
    asm volatile("mma.sync.aligned.m16n8k16.row.col.f32.f16.f16.f32 " \
        "{%0,%1,%2,%3}, {%4,%5,%6,%7}, {%8,%9}, {%0,%1,%2,%3};" \
        : "+f"((cr)[0]), "+f"((cr)[1]), "+f"((cr)[2]), "+f"((cr)[3]) \
        : "r"((a)[0]), "r"((a)[1]), "r"((a)[2]), "r"((a)[3]), "r"(b0), "r"(b1))

#define CP16(dst, src) \
    asm volatile("cp.async.ca.shared.global [%0], [%1], 16;" \
                 :: "r"(dst), "l"(src) : "memory")
#define CP_COMMIT() asm volatile("cp.async.commit_group;" ::: "memory")
#define CP_WAIT(n)  asm volatile("cp.async.wait_group %0;" :: "n"(n) : "memory")

__device__ __forceinline__ void split_sts(char* hip, char* lop, float4 v) {
    uint32_t h0 = __byte_perm(__float_as_uint(v.x), __float_as_uint(v.y), 0x7632);
    uint32_t h1 = __byte_perm(__float_as_uint(v.z), __float_as_uint(v.w), 0x7632);
    float lx = v.x - __uint_as_float(__float_as_uint(v.x) & 0xffff0000u);
    float ly = v.y - __uint_as_float(__float_as_uint(v.y) & 0xffff0000u);
    float lz = v.z - __uint_as_float(__float_as_uint(v.z) & 0xffff0000u);
    float lw = v.w - __uint_as_float(__float_as_uint(v.w) & 0xffff0000u);
    uint32_t l0, l1;
    CVT_BF2(l0, ly, lx);
    CVT_BF2(l1, lw, lz);
    *(uint2*)hip = make_uint2(h0, h1);
    *(uint2*)lop = make_uint2(l0, l1);
}

// ---------------------------------------------------------------------------
// Elementwise fp32 -> bf16 hi/lo split (for GEMM operands)
// ---------------------------------------------------------------------------
__global__ void __launch_bounds__(256) split_f32(
    const float4* __restrict__ src, uint2* __restrict__ hi,
    uint2* __restrict__ lo, int n4)
{
    int i = blockIdx.x * 256 + threadIdx.x;
    if (i >= n4) return;
    float4 v = src[i];
    uint32_t h0 = __byte_perm(__float_as_uint(v.x), __float_as_uint(v.y), 0x7632);
    uint32_t h1 = __byte_perm(__float_as_uint(v.z), __float_as_uint(v.w), 0x7632);
    float lx = v.x - __uint_as_float(__float_as_uint(v.x) & 0xffff0000u);
    float ly = v.y - __uint_as_float(__float_as_uint(v.y) & 0xffff0000u);
    float lz = v.z - __uint_as_float(__float_as_uint(v.z) & 0xffff0000u);
    float lw = v.w - __uint_as_float(__float_as_uint(v.w) & 0xffff0000u);
    uint32_t l0, l1;
    CVT_BF2(l0, ly, lx);
    CVT_BF2(l1, lw, lz);
    hi[i] = make_uint2(h0, h1);
    lo[i] = make_uint2(l0, l1);
}

// ---------------------------------------------------------------------------
// Pre-split bf16x3 NT GEMM + bias via mma.sync + cp.async.
// Inputs already split into hi/lo bf16 (row-major, K contiguous).
// BM=BN=128, BK=32. 256 thr = 8 warps (4m x 2n), warp tile 32x64.
// smem rows: 64B data + 16B pad (GROWB=80) -> conflict-free ldmatrix.
// ---------------------------------------------------------------------------
#define GROWB   80
#define GMAT    (128 * GROWB)              /* 10240 B */
#define GSTAGE  (4 * GMAT)                 /* Ah|Al|Bh|Bl = 40960 B */
#define GSMEM   (2 * GSTAGE)

__global__ void __launch_bounds__(256, 1) gemm_bf16p(
    const __nv_bfloat16* __restrict__ Ah, const __nv_bfloat16* __restrict__ Al,
    const __nv_bfloat16* __restrict__ Bh, const __nv_bfloat16* __restrict__ Bl,
    const float* __restrict__ bias, float* __restrict__ C,
    int M, int N, int K)
{
    extern __shared__ char smem[];
    const uint32_t sbase = smem_u32(smem);

    const int tid  = threadIdx.x;
    const int wid  = tid >> 5;
    const int lane = tid & 31;
    const int bm = blockIdx.y << 7;
    const int bn = blockIdx.x << 7;

    const int m0 = (wid & 3) << 5;
    const int n0 = (wid >> 2) << 6;

    float c[2][8][4];
#pragma unroll
    for (int mt = 0; mt < 2; ++mt)
#pragma unroll
        for (int nt = 0; nt < 8; ++nt)
#pragma unroll
            for (int q = 0; q < 4; ++q) c[mt][nt][q] = 0.f;

    const int a_row = lane & 15;
    const int a_col = ((lane >> 4) & 1) << 3;
    const int b_mat = lane >> 3;
    const int b_nrow = (lane & 7) + ((b_mat & 1) << 3);
    const int b_kcol = (b_mat >> 1) << 3;

    // loader: thread -> row (tid>>1), 32B chunk pair (tid&1)
    const int lrow = tid >> 1;
    const int lseg = (tid & 1) << 1;       // seg base 0 or 2 (16B units)
    const __nv_bfloat16* Ahg = Ah + (size_t)(bm + lrow) * K + lseg * 8;
    const __nv_bfloat16* Alg = Al + (size_t)(bm + lrow) * K + lseg * 8;
    const __nv_bfloat16* Bhg = Bh + (size_t)(bn + lrow) * K + lseg * 8;
    const __nv_bfloat16* Blg = Bl + (size_t)(bn + lrow) * K + lseg * 8;
    const uint32_t sto = (uint32_t)(lrow * GROWB + lseg * 16);

    const int KT = K >> 5;

    // prologue: stage 0
    {
        const uint32_t s0 = sbase + sto;
        CP16(s0,             Ahg);      CP16(s0 + 16,             Ahg + 8);
        CP16(s0 + GMAT,      Alg);      CP16(s0 + GMAT + 16,      Alg + 8);
        CP16(s0 + 2 * GMAT,  Bhg);      CP16(s0 + 2 * GMAT + 16,  Bhg + 8);
        CP16(s0 + 3 * GMAT,  Blg);      CP16(s0 + 3 * GMAT + 16,  Blg + 8);
        CP_COMMIT();
    }

    for (int it = 0; it < KT; ++it) {
        const int buf = it & 1;
        if (it + 1 < KT) {
            const uint32_t s1 = sbase + ((it + 1) & 1) * GSTAGE + sto;
            const size_t go = (size_t)(it + 1) * 32;
            CP16(s1,            Ahg + go);  CP16(s1 + 16,            Ahg + go + 8);
            CP16(s1 + GMAT,     Alg + go);  CP16(s1 + GMAT + 16,     Alg + go + 8);
            CP16(s1 + 2 * GMAT, Bhg + go);  CP16(s1 + 2 * GMAT + 16, Bhg + go + 8);
            CP16(s1 + 3 * GMAT, Blg + go);  CP16(s1 + 3 * GMAT + 16, Blg + go + 8);
            CP_COMMIT();
            CP_WAIT(1);
        } else {
            CP_WAIT(0);
        }
        __syncthreads();

        const uint32_t sA  = sbase + buf * GSTAGE;
        const uint32_t sAl = sA + GMAT;
        const uint32_t sB  = sA + 2 * GMAT;
        const uint32_t sBl = sA + 3 * GMAT;

#pragma unroll
        for (int ks = 0; ks < 2; ++ks) {
            const int kb = ks << 4;
            uint32_t ah[2][4], al[2][4], bh[4][4], bl[4][4];
            const uint32_t aoff = (uint32_t)(a_row * GROWB + (kb + a_col) * 2);
            const uint32_t boff = (uint32_t)(b_nrow * GROWB + (kb + b_kcol) * 2);
#pragma unroll
            for (int mt = 0; mt < 2; ++mt) {
                const uint32_t mo = (uint32_t)((m0 + mt * 16) * GROWB);
                LDSM4(ah[mt], sA  + mo + aoff);
                LDSM4(al[mt], sAl + mo + aoff);
            }
#pragma unroll
            for (int nq = 0; nq < 4; ++nq) {
                const uint32_t no = (uint32_t)((n0 + nq * 16) * GROWB);
                LDSM4(bh[nq], sB  + no + boff);
                LDSM4(bl[nq], sBl + no + boff);
            }
#pragma unroll
            for (int mt = 0; mt < 2; ++mt)
#pragma unroll
                for (int nt = 0; nt < 8; ++nt) {
                    const int nq = nt >> 1, sel = nt & 1;
                    MMA_BF16(c[mt][nt], ah[mt], bh[nq][sel], bh[nq][sel + 2]);
                    MMA_BF16(c[mt][nt], ah[mt], bl[nq][sel], bl[nq][sel + 2]);
                    MMA_BF16(c[mt][nt], al[mt], bh[nq][sel], bh[nq][sel + 2]);
                }
        }
        __syncthreads();
    }

    const int grp = lane >> 2, tig = lane & 3;
#pragma unroll
    for (int nt = 0; nt < 8; ++nt) {
        const int col = bn + n0 + nt * 8 + tig * 2;
        const float2 bv = *(const float2*)&bias[col];
#pragma unroll
        for (int mt = 0; mt < 2; ++mt) {
            const int row = bm + m0 + mt * 16 + grp;
            float2 v0 = make_float2(c[mt][nt][0] + bv.x, c[mt][nt][1] + bv.y);
            float2 v1 = make_float2(c[mt][nt][2] + bv.x, c[mt][nt][3] + bv.y);
            *(float2*)&C[(size_t)row * N + col]       = v0;
            *(float2*)&C[(size_t)(row + 8) * N + col] = v1;
        }
    }
}

// ---------------------------------------------------------------------------
// Pre-pass: Q (scaled) and K -> bf16 hi/lo, layout [bh][s][d]
// ---------------------------------------------------------------------------
__global__ void __launch_bounds__(256) convert_qk(
    const float* __restrict__ qkv,
    __nv_bfloat16* __restrict__ qh, __nv_bfloat16* __restrict__ ql,
    __nv_bfloat16* __restrict__ kh, __nv_bfloat16* __restrict__ kl)
{
    const int gw   = blockIdx.x * 8 + (threadIdx.x >> 5);
    const int lane = threadIdx.x & 31;
    const int bh = gw >> 11;
    const int s  = gw & 2047;
    const int b  = bh >> 4;
    const int h  = bh & 15;

    const float* src = qkv + ((size_t)(b * SEQ + s)) * QKV_N + h * HEAD_DIM + lane * 4;
    float4 q = *(const float4*)src;
    float4 k = *(const float4*)(src + HIDDEN);
    q.x *= SOFTMAX_SCALE; q.y *= SOFTMAX_SCALE;
    q.z *= SOFTMAX_SCALE; q.w *= SOFTMAX_SCALE;

    const size_t dst = ((size_t)gw) * HEAD_DIM + lane * 4;
    split_sts((char*)(qh + dst), (char*)(ql + dst), q);
    split_sts((char*)(kh + dst), (char*)(kl + dst), k);
}

// ---------------------------------------------------------------------------
// Pre-pass: V -> fp16 hi/lo, transposed to [bh][d][s]
// ---------------------------------------------------------------------------
__global__ void __launch_bounds__(256) convert_v(
    const float* __restrict__ qkv,
    __half* __restrict__ vh, __half* __restrict__ vl)
{
    __shared__ float t[32][33];

    const int s0 = blockIdx.x << 5;
    const int d0 = blockIdx.y << 5;
    const int bh = blockIdx.z;
    const int b  = bh >> 4;
    const int h  = bh & 15;

    const int col  = threadIdx.x & 31;
    const int rowb = threadIdx.x >> 5;

    const size_t inbase = ((size_t)(b * SEQ + s0)) * QKV_N + 2 * HIDDEN + h * HEAD_DIM + d0;
#pragma unroll
    for (int r = rowb; r < 32; r += 8)
        t[r][col] = qkv[inbase + (size_t)r * QKV_N + col];
    __syncthreads();

    const size_t outbase = ((size_t)bh * HEAD_DIM + d0) * SEQ + s0;
#pragma unroll
    for (int r = rowb; r < 32; r += 8) {
        float v = t[col][r];
        __half hi = __float2half_rn(v);
        __half lo = __float2half_rn(v - __half2float(hi));
        vh[outbase + (size_t)r * SEQ + col] = hi;
        vl[outbase + (size_t)r * SEQ + col] = lo;
    }
}

// ---------------------------------------------------------------------------
// Flash attention on tensor cores (q-tile 128, key-tile 64, 8 warps).
// Output written as bf16 hi/lo (feeds pre-split dense GEMM directly).
// ---------------------------------------------------------------------------
#define QSTR 272
#define VSTR 144
#define SQH 0
#define SQL (SQH + 128 * QSTR)
#define SKH (SQL + 128 * QSTR)
#define SKL (SKH + 64 * QSTR)
#define SVH (SKL + 64 * QSTR)
#define SVL (SVH + 128 * VSTR)
#define ATTN_SMEM (SVL + 128 * VSTR)

__global__ void __launch_bounds__(256, 1) attn_mma(
    const __nv_bfloat16* __restrict__ qh, const __nv_bfloat16* __restrict__ ql,
    const __nv_bfloat16* __restrict__ kh, const __nv_bfloat16* __restrict__ kl,
    const __half* __restrict__ vh, const __half* __restrict__ vl,
    __nv_bfloat16* __restrict__ oh, __nv_bfloat16* __restrict__ ol)
{
    extern __shared__ char sm[];
    const uint32_t sbase = smem_u32(sm);

    const int iq = (int)gridDim.x - 1 - (int)blockIdx.x;   // heavy tiles first
    const int bh = blockIdx.y;
    const int b  = bh >> 4;
    const int h  = bh & 15;
    const int tid  = threadIdx.x;
    const int wid  = tid >> 5;
    const int lane = tid & 31;
    const int q0 = iq << 7;
    const int m0 = wid << 4;

    {
        const uint4* qhg = (const uint4*)(qh + ((size_t)bh * SEQ + q0) * HEAD_DIM);
        const uint4* qlg = (const uint4*)(ql + ((size_t)bh * SEQ + q0) * HEAD_DIM);
#pragma unroll
        for (int i = tid; i < 2048; i += 256) {
            const int row = i >> 4, seg = i & 15;
            *(uint4*)(sm + SQH + row * QSTR + seg * 16) = qhg[row * 16 + seg];
            *(uint4*)(sm + SQL + row * QSTR + seg * 16) = qlg[row * 16 + seg];
        }
    }

    float co[16][4];
#pragma unroll
    for (int t = 0; t < 16; ++t)
#pragma unroll
        for (int q = 0; q < 4; ++q) co[t][q] = 0.f;
    float mr0 = -1e30f, mr1 = -1e30f, lr0 = 0.f, lr1 = 0.f;

    const int a_row = lane & 15;
    const int a_col = ((lane >> 4) & 1) << 3;
    const int b_mat = lane >> 3;
    const int b_nrow = (lane & 7) + ((b_mat & 1) << 3);
    const int b_kcol = (b_mat >> 1) << 3;

    const int nkt = 2 * (iq + 1);
    for (int jt = 0; jt < nkt; ++jt) {
        const int kt0 = jt << 6;
        {
            const uint4* khg = (const uint4*)(kh + ((size_t)bh * SEQ + kt0) * HEAD_DIM);
            const uint4* klg = (const uint4*)(kl + ((size_t)bh * SEQ + kt0) * HEAD_DIM);
#pragma unroll
            for (int i = tid; i < 1024; i += 256) {
                const int row = i >> 4, seg = i & 15;
                *(uint4*)(sm + SKH + row * QSTR + seg * 16) = khg[row * 16 + seg];
                *(uint4*)(sm + SKL + row * QSTR + seg * 16) = klg[row * 16 + seg];
            }
        }
        {
#pragma unroll
            for (int i = tid; i < 1024; i += 256) {
                const int d = i >> 3, seg = i & 7;
                const uint4* vhg = (const uint4*)(vh + ((size_t)bh * HEAD_DIM + d) * SEQ + kt0);
                const uint4* vlg = (const uint4*)(vl + ((size_t)bh * HEAD_DIM + d) * SEQ + kt0);
                *(uint4*)(sm + SVH + d * VSTR + seg * 16) = vhg[seg];
                *(uint4*)(sm + SVL + d * VSTR + seg * 16) = vlg[seg];
            }
        }
        __syncthreads();

        float cs[8][4];
#pragma unroll
        for (int t = 0; t < 8; ++t)
#pragma unroll
            for (int q = 0; q < 4; ++q) cs[t][q] = 0.f;

#pragma unroll
        for (int ks = 0; ks < 8; ++ks) {
            const int kb = ks << 4;
            uint32_t ah[4], al[4], bhf[4][4], blf[4][4];
            const uint32_t aoff = (uint32_t)((m0 + a_row) * QSTR + (kb + a_col) * 2);
            LDSM4(ah, sbase + SQH + aoff);
            LDSM4(al, sbase + SQL + aoff);
            const uint32_t boff = (uint32_t)(b_nrow * QSTR + (kb + b_kcol) * 2);
#pragma unroll
            for (int nq = 0; nq < 4; ++nq) {
                const uint32_t no = (uint32_t)(nq * 16 * QSTR);
                LDSM4(bhf[nq], sbase + SKH + no + boff);
                LDSM4(blf[nq], sbase + SKL + no + boff);
            }
#pragma unroll
            for (int nt = 0; nt < 8; ++nt) {
                const int nq = nt >> 1, sel = nt & 1;
                MMA_BF16(cs[nt], ah, bhf[nq][sel], bhf[nq][sel + 2]);
                MMA_BF16(cs[nt], ah, blf[nq][sel], blf[nq][sel + 2]);
                MMA_BF16(cs[nt], al, bhf[nq][sel], bhf[nq][sel + 2]);
            }
        }

        if (jt >= 2 * iq) {
            const int rg0 = q0 + m0 + (lane >> 2);
            const int rg1 = rg0 + 8;
            const int cb  = kt0 + ((lane & 3) << 1);
#pragma unroll
            for (int nt = 0; nt < 8; ++nt) {
                const int c0 = cb + nt * 8;
                if (c0     > rg0) cs[nt][0] = -1e30f;
                if (c0 + 1 > rg0) cs[nt][1] = -1e30f;
                if (c0     > rg1) cs[nt][2] = -1e30f;
                if (c0 + 1 > rg1) cs[nt][3] = -1e30f;
            }
        }

        float mx0 = cs[0][0], mx1 = cs[0][2];
#pragma unroll
        for (int nt = 0; nt < 8; ++nt) {
            mx0 = fmaxf(mx0, fmaxf(cs[nt][0], cs[nt][1]));
            mx1 = fmaxf(mx1, fmaxf(cs[nt][2], cs[nt][3]));
        }
        mx0 = fmaxf(mx0, __shfl_xor_sync(0xffffffffu, mx0, 1));
        mx0 = fmaxf(mx0, __shfl_xor_sync(0xffffffffu, mx0, 2));
        mx1 = fmaxf(mx1, __shfl_xor_sync(0xffffffffu, mx1, 1));
        mx1 = fmaxf(mx1, __shfl_xor_sync(0xffffffffu, mx1, 2));

        const float mn0 = fmaxf(mr0, mx0);
        const float mn1 = fmaxf(mr1, mx1);
        const float corr0 = fast_exp2((mr0 - mn0) * LOG2E);
        const float corr1 = fast_exp2((mr1 - mn1) * LOG2E);
        mr0 = mn0; mr1 = mn1;

        float rs0 = 0.f, rs1 = 0.f;
#pragma unroll
        for (int nt = 0; nt < 8; ++nt) {
            float p0 = fast_exp2((cs[nt][0] - mn0) * LOG2E);
            float p1 = fast_exp2((cs[nt][1] - mn0) * LOG2E);
            float p2 = fast_exp2((cs[nt][2] - mn1) * LOG2E);
            float p3 = fast_exp2((cs[nt][3] - mn1) * LOG2E);
            cs[nt][0] = p0; cs[nt][1] = p1; cs[nt][2] = p2; cs[nt][3] = p3;
            rs0 += p0 + p1; rs1 += p2 + p3;
        }
        rs0 += __shfl_xor_sync(0xffffffffu, rs0, 1);
        rs0 += __shfl_xor_sync(0xffffffffu, rs0, 2);
        rs1 += __shfl_xor_sync(0xffffffffu, rs1, 1);
        rs1 += __shfl_xor_sync(0xffffffffu, rs1, 2);
        lr0 = lr0 * corr0 + rs0;
        lr1 = lr1 * corr1 + rs1;
#pragma unroll
        for (int t = 0; t < 16; ++t) {
            co[t][0] *= corr0; co[t][1] *= corr0;
            co[t][2] *= corr1; co[t][3] *= corr1;
        }

        uint32_t pa[4][4];
#pragma unroll
        for (int t = 0; t < 4; ++t) {
            PACK_F16(pa[t][0], cs[2 * t][1],     cs[2 * t][0]);
            PACK_F16(pa[t][1], cs[2 * t][3],     cs[2 * t][2]);
            PACK_F16(pa[t][2], cs[2 * t + 1][1], cs[2 * t + 1][0]);
            PACK_F16(pa[t][3], cs[2 * t + 1][3], cs[2 * t + 1][2]);
        }

#pragma unroll
        for (int ks = 0; ks < 4; ++ks) {
            const uint32_t voff = (uint32_t)(b_nrow * VSTR + ((ks << 4) + b_kcol) * 2);
#pragma unroll
            for (int nq = 0; nq < 8; ++nq) {
                uint32_t vhf[4], vlf[4];
                const uint32_t no = (uint32_t)(nq * 16 * VSTR);
                LDSM4(vhf, sbase + SVH + no + voff);
                LDSM4(vlf, sbase + SVL + no + voff);
                MMA_F16(co[nq * 2],     pa[ks], vhf[0], vhf[2]);
                MMA_F16(co[nq * 2],     pa[ks], vlf[0], vlf[2]);
                MMA_F16(co[nq * 2 + 1], pa[ks], vhf[1], vhf[3]);
                MMA_F16(co[nq * 2 + 1], pa[ks], vlf[1], vlf[3]);
            }
        }
        __syncthreads();
    }

    // ---- epilogue: normalize, split to bf16 hi/lo ----
    const float inv0 = 1.f / lr0;
    const float inv1 = 1.f / lr1;
    const size_t row0 = (size_t)(b * SEQ + q0 + m0 + (lane >> 2));
#pragma unroll
    for (int t = 0; t < 16; ++t) {
        const int col = h * HEAD_DIM + t * 8 + ((lane & 3) << 1);
        float a0 = co[t][0] * inv0, a1 = co[t][1] * inv0;
        float b0v = co[t][2] * inv1, b1v = co[t][3] * inv1;
        uint32_t h0 = __byte_perm(__float_as_uint(a0), __float_as_uint(a1), 0x7632);
        uint32_t h1 = __byte_perm(__float_as_uint(b0v), __float_as_uint(b1v), 0x7632);
        float l0a = a0 - __uint_as_float(__float_as_uint(a0) & 0xffff0000u);
        float l1a = a1 - __uint_as_float(__float_as_uint(a1) & 0xffff0000u);
        float l0b = b0v - __uint_as_float(__float_as_uint(b0v) & 0xffff0000u);
        float l1b = b1v - __uint_as_float(__float_as_uint(b1v) & 0xffff0000u);
        uint32_t lo0, lo1;
        CVT_BF2(lo0, l1a, l0a);
        CVT_BF2(lo1, l1b, l0b);
        *(uint32_t*)&oh[row0 * HIDDEN + col]       = h0;
        *(uint32_t*)&ol[row0 * HIDDEN + col]       = lo0;
        *(uint32_t*)&oh[(row0 + 8) * HIDDEN + col] = h1;
        *(uint32_t*)&ol[(row0 + 8) * HIDDEN + col] = lo1;
    }
}

// ---------------------------------------------------------------------------
// Launch
// ---------------------------------------------------------------------------
extern "C" void kernel_launch(void* const* d_in, const int* in_sizes, int n_in,
                              void* d_out, int out_size)
{
    const float* hidden  = (const float*)d_in[0];
    const float* w_qkv   = (const float*)d_in[1];
    const float* b_qkv   = (const float*)d_in[2];
    const float* w_dense = (const float*)d_in[3];
    const float* b_dense = (const float*)d_in[4];
    float* out = (float*)d_out;

    float* qkv_p;
    __nv_bfloat16 *hh, *hl, *wqh, *wql, *wdh, *wdl, *ath, *atl;
    __nv_bfloat16 *qh_p, *ql_p, *kh_p, *kl_p;
    __half *vh_p, *vl_p;
    cudaGetSymbolAddress((void**)&qkv_p, g_qkv);
    cudaGetSymbolAddress((void**)&hh,  g_hh);
    cudaGetSymbolAddress((void**)&hl,  g_hl);
    cudaGetSymbolAddress((void**)&wqh, g_wqh);
    cudaGetSymbolAddress((void**)&wql, g_wql);
    cudaGetSymbolAddress((void**)&wdh, g_wdh);
    cudaGetSymbolAddress((void**)&wdl, g_wdl);
    cudaGetSymbolAddress((void**)&ath, g_ath);
    cudaGetSymbolAddress((void**)&atl, g_atl);
    cudaGetSymbolAddress((void**)&qh_p, g_qh);
    cudaGetSymbolAddress((void**)&ql_p, g_ql);
    cudaGetSymbolAddress((void**)&kh_p, g_kh);
    cudaGetSymbolAddress((void**)&kl_p, g_kl);
    cudaGetSymbolAddress((void**)&vh_p, g_vh);
    cudaGetSymbolAddress((void**)&vl_p, g_vl);

    cudaFuncSetAttribute(gemm_bf16p,
                         cudaFuncAttributeMaxDynamicSharedMemorySize, GSMEM);
    cudaFuncSetAttribute(attn_mma,
                         cudaFuncAttributeMaxDynamicSharedMemorySize, ATTN_SMEM);

    dim3 blk(256);

    // 0) pre-split GEMM operands
    {
        int n4 = TOKENS * HIDDEN / 4;
        split_f32<<<(n4 + 255) / 256, blk>>>((const float4*)hidden,
                                             (uint2*)hh, (uint2*)hl, n4);
        n4 = QKV_N * HIDDEN / 4;
        split_f32<<<(n4 + 255) / 256, blk>>>((const float4*)w_qkv,
                                             (uint2*)wqh, (uint2*)wql, n4);
        n4 = HIDDEN * HIDDEN / 4;
        split_f32<<<(n4 + 255) / 256, blk>>>((const float4*)w_dense,
                                             (uint2*)wdh, (uint2*)wdl, n4);
    }

    // 1) QKV projection
    gemm_bf16p<<<dim3(QKV_N / 128, TOKENS / 128), blk, GSMEM>>>(
        hh, hl, wqh, wql, b_qkv, qkv_p, TOKENS, QKV_N, HIDDEN);

    // 2) Convert Q (scaled), K to bf16 hi/lo
    convert_qk<<<(BH * SEQ) / 8, blk>>>(qkv_p, qh_p, ql_p, kh_p, kl_p);

    // 3) Convert + transpose V to fp16 hi/lo
    convert_v<<<dim3(SEQ / 32, HEAD_DIM / 32, BH), blk>>>(qkv_p, vh_p, vl_p);

    // 4) Tensor-core flash attention (bf16 hi/lo out)
    attn_mma<<<dim3(SEQ / 128, BH), blk, ATTN_SMEM>>>(
        qh_p, ql_p, kh_p, kl_p, vh_p, vl_p, ath, atl);

    // 5) Dense projection
    gemm_bf16p<<<dim3(HIDDEN / 128, TOKENS / 128), blk, GSMEM>>>(
        ath, atl, wdh, wdl, b_dense, out, TOKENS, HIDDEN, HIDDEN);
}